// round 7
// baseline (speedup 1.0000x reference)
#include <cuda_runtime.h>

#define N_ITEMS 20000
#define ALPHA 0.2f
#define GRID 625   // 625 CTAs x 8 warps = 5000 warps x 4 rows = 20000

__global__ __launch_bounds__(256) void gat_kernel(
    const float* __restrict__ item,
    const float* __restrict__ ent,
    const int*   __restrict__ adj,
    const float* __restrict__ W,
    const float* __restrict__ a,
    float*       __restrict__ out)
{
    __shared__ float wa1s[64];
    __shared__ float wa2s[64];

    const int t    = threadIdx.x;
    const int lane = t & 31;
    const int w    = t >> 5;
    const int q    = lane & 7;    // f-octet: f = q*8 .. q*8+7
    const int ml   = lane >> 3;   // m_local 0..3

    // --- Prologue: wa1 = W@a1, wa2 = W@a2 (once per CTA) ---
    {
        const int f = t >> 2, qq = t & 3;
        const float* wr = W + f * 64 + qq * 16;
        float p1 = 0.f, p2 = 0.f;
#pragma unroll
        for (int i = 0; i < 4; ++i) {
            float4 wv = *reinterpret_cast<const float4*>(wr + i * 4);
            float4 y1 = *reinterpret_cast<const float4*>(a + qq * 16 + i * 4);
            float4 y2 = *reinterpret_cast<const float4*>(a + 64 + qq * 16 + i * 4);
            p1 += wv.x * y1.x + wv.y * y1.y + wv.z * y1.z + wv.w * y1.w;
            p2 += wv.x * y2.x + wv.y * y2.y + wv.z * y2.z + wv.w * y2.w;
        }
        p1 += __shfl_xor_sync(0xffffffffu, p1, 1);
        p1 += __shfl_xor_sync(0xffffffffu, p1, 2);
        p2 += __shfl_xor_sync(0xffffffffu, p2, 1);
        p2 += __shfl_xor_sync(0xffffffffu, p2, 2);
        if (qq == 0) { wa1s[f] = p1; wa2s[f] = p2; }
    }
    __syncthreads();

    const float4 w2a = *reinterpret_cast<const float4*>(&wa2s[q * 8]);
    const float4 w2b = *reinterpret_cast<const float4*>(&wa2s[q * 8 + 4]);
    const float  wa1a = wa1s[lane];
    const float  wa1b = wa1s[32 + lane];

    const int gw = blockIdx.x * 8 + w;   // 0..4999

    // Prefetch row 0's adj + item
    int   j0  = adj[(size_t)(gw * 4) * 64 + lane];
    int   j1  = adj[(size_t)(gw * 4) * 64 + 32 + lane];
    float it0 = item[(size_t)(gw * 4) * 64 + lane];
    float it1 = item[(size_t)(gw * 4) * 64 + 32 + lane];

#pragma unroll 1
    for (int i = 0; i < 4; ++i) {
        const int n = gw * 4 + i;
        const size_t b = (size_t)n * 64;
        const float* eb = ent + b * 64;

        // chunk 0: flags + loads FIRST (so s1's shfl chain overlaps LDG latency)
        int fcur = __shfl_sync(0xffffffffu, j0, ml);
        float4 vc0, vc1;
        if (fcur > 0) {
            const float* p = eb + ml * 64 + q * 8;
            vc0 = *reinterpret_cast<const float4*>(p);
            vc1 = *reinterpret_cast<const float4*>(p + 4);
        } else {
            vc0 = make_float4(0.f, 0.f, 0.f, 0.f);
            vc1 = make_float4(0.f, 0.f, 0.f, 0.f);
        }

        // prefetch next row's adj/item while this row streams
        int j0n = 0, j1n = 0;
        float it0n = 0.f, it1n = 0.f;
        if (i < 3) {
            j0n  = adj[b + 64 + lane];
            j1n  = adj[b + 96 + lane];
            it0n = item[b + 64 + lane];
            it1n = item[b + 96 + lane];
        }

        // s1 = item[n] . wa1 (broadcast to all lanes)
        float s1 = it0 * wa1a + it1 * wa1b;
#pragma unroll
        for (int o = 16; o > 0; o >>= 1) s1 += __shfl_xor_sync(0xffffffffu, s1, o);

        float4 acc0 = make_float4(0.f, 0.f, 0.f, 0.f);
        float4 acc1 = make_float4(0.f, 0.f, 0.f, 0.f);
        float  sm   = 0.f;

#pragma unroll
        for (int c = 0; c < 16; ++c) {
            // prefetch chunk c+1 (flags from regs via shfl, predicated loads)
            int fnext = 0;
            float4 vn0 = make_float4(0.f, 0.f, 0.f, 0.f);
            float4 vn1 = make_float4(0.f, 0.f, 0.f, 0.f);
            if (c < 15) {
                const int cn  = c + 1;
                const int src = (cn * 4 + ml) & 31;
                fnext = __shfl_sync(0xffffffffu, (cn < 8) ? j0 : j1, src);
                if (fnext > 0) {
                    const float* p = eb + (cn * 4 + ml) * 64 + q * 8;
                    vn0 = *reinterpret_cast<const float4*>(p);
                    vn1 = *reinterpret_cast<const float4*>(p + 4);
                }
            }

            // d_m = entity[m] . wa2 (reduce over 8 q-lanes)
            float d = vc0.x * w2a.x + vc0.y * w2a.y + vc0.z * w2a.z + vc0.w * w2a.w
                    + vc1.x * w2b.x + vc1.y * w2b.y + vc1.z * w2b.z + vc1.w * w2b.w;
            d += __shfl_xor_sync(0xffffffffu, d, 1);
            d += __shfl_xor_sync(0xffffffffu, d, 2);
            d += __shfl_xor_sync(0xffffffffu, d, 4);

            float e = s1 + d;
            e = e > 0.f ? e : ALPHA * e;
            const float x = (fcur > 0) ? __expf(e) : 0.f;  // unnormalized att
            sm += x;

            acc0.x = fmaf(x, vc0.x, acc0.x);
            acc0.y = fmaf(x, vc0.y, acc0.y);
            acc0.z = fmaf(x, vc0.z, acc0.z);
            acc0.w = fmaf(x, vc0.w, acc0.w);
            acc1.x = fmaf(x, vc1.x, acc1.x);
            acc1.y = fmaf(x, vc1.y, acc1.y);
            acc1.z = fmaf(x, vc1.z, acc1.z);
            acc1.w = fmaf(x, vc1.w, acc1.w);

            if (c < 15) { vc0 = vn0; vc1 = vn1; fcur = fnext; }
        }

        // Reduce acc + sm across the 4 m_local groups (lane bits 3,4)
#pragma unroll
        for (int o = 8; o <= 16; o <<= 1) {
            acc0.x += __shfl_xor_sync(0xffffffffu, acc0.x, o);
            acc0.y += __shfl_xor_sync(0xffffffffu, acc0.y, o);
            acc0.z += __shfl_xor_sync(0xffffffffu, acc0.z, o);
            acc0.w += __shfl_xor_sync(0xffffffffu, acc0.w, o);
            acc1.x += __shfl_xor_sync(0xffffffffu, acc1.x, o);
            acc1.y += __shfl_xor_sync(0xffffffffu, acc1.y, o);
            acc1.z += __shfl_xor_sync(0xffffffffu, acc1.z, o);
            acc1.w += __shfl_xor_sync(0xffffffffu, acc1.w, o);
            sm     += __shfl_xor_sync(0xffffffffu, sm, o);
        }

        const float inv = 1.0f / sm;  // normalize once, at the end
        if (ml == 0) {
            const float4 i0 = *reinterpret_cast<const float4*>(item + b + q * 8);
            const float4 i1 = *reinterpret_cast<const float4*>(item + b + q * 8 + 4);
            float4 r0, r1;
            r0.x = fmaf(acc0.x, inv, i0.x);
            r0.y = fmaf(acc0.y, inv, i0.y);
            r0.z = fmaf(acc0.z, inv, i0.z);
            r0.w = fmaf(acc0.w, inv, i0.w);
            r1.x = fmaf(acc1.x, inv, i1.x);
            r1.y = fmaf(acc1.y, inv, i1.y);
            r1.z = fmaf(acc1.z, inv, i1.z);
            r1.w = fmaf(acc1.w, inv, i1.w);
            *reinterpret_cast<float4*>(out + b + q * 8)     = r0;
            *reinterpret_cast<float4*>(out + b + q * 8 + 4) = r1;
        }

        j0 = j0n; j1 = j1n; it0 = it0n; it1 = it1n;
    }
}

extern "C" void kernel_launch(void* const* d_in, const int* in_sizes, int n_in,
                              void* d_out, int out_size) {
    const float* item = (const float*)d_in[0];
    const float* ent  = (const float*)d_in[1];
    const int*   adj  = (const int*)d_in[2];
    const float* W    = (const float*)d_in[3];
    const float* a    = (const float*)d_in[4];
    float* out = (float*)d_out;

    gat_kernel<<<GRID, 256>>>(item, ent, adj, W, a, out);
}

// round 8
// speedup vs baseline: 1.4224x; 1.4224x over previous
#include <cuda_runtime.h>

#define N_ITEMS 20000
#define ALPHA 0.2f
#define GRID 608   // 4 CTAs/SM x 152 SMs (persistent)

// Per-lane adj flags + item values for row n (per-warp redundant; L1 broadcast).
#define LOADJI(n, j0, j1, i0, i1)                                            \
    {                                                                        \
        const size_t _b = (size_t)(n) * 64;                                  \
        j0 = adj[_b + lane];                                                 \
        j1 = adj[_b + 32 + lane];                                            \
        i0 = item[_b + lane];                                                \
        i1 = item[_b + 32 + lane];                                           \
    }

// 4-bit mask for this thread's rows m = k*16+grp from per-lane adj regs.
#define MASKOF(j0, j1, mk)                                                   \
    {                                                                        \
        const int _f0 = __shfl_sync(0xffffffffu, j0, grp);                   \
        const int _f1 = __shfl_sync(0xffffffffu, j0, 16 + grp);              \
        const int _f2 = __shfl_sync(0xffffffffu, j1, grp);                   \
        const int _f3 = __shfl_sync(0xffffffffu, j1, 16 + grp);              \
        mk = (_f0 > 0 ? 1 : 0) | (_f1 > 0 ? 2 : 0)                           \
           | (_f2 > 0 ? 4 : 0) | (_f3 > 0 ? 8 : 0);                          \
    }

// Predicated tile load: only rows with adj=1 touch DRAM (~50% skipped).
#define LOADT_P(n, v, mk)                                                    \
    {                                                                        \
        const float* _eb = ent + (size_t)(n) * 4096;                         \
        _Pragma("unroll")                                                    \
        for (int _k = 0; _k < 4; ++_k) {                                     \
            if ((mk >> _k) & 1)                                              \
                v[_k] = *reinterpret_cast<const float4*>(_eb + _k * 1024 + t * 4); \
            else                                                             \
                v[_k] = make_float4(0.f, 0.f, 0.f, 0.f);                     \
        }                                                                    \
    }

// Per-row processing: deferred-normalization softmax (no per-warp softmax
// shfl chains; divide once in the epilogue).
#define BODY(n, v, mk, it0, it1)                                             \
    {                                                                        \
        const size_t _b = (size_t)(n) * 64;                                  \
                                                                             \
        /* d-phase: 4 partial dots, transpose-reduce over 16 lanes (5 shfl) */\
        float _d0 = v[0].x * w2.x + v[0].y * w2.y + v[0].z * w2.z + v[0].w * w2.w; \
        float _d1 = v[1].x * w2.x + v[1].y * w2.y + v[1].z * w2.z + v[1].w * w2.w; \
        float _d2 = v[2].x * w2.x + v[2].y * w2.y + v[2].z * w2.z + v[2].w * w2.w; \
        float _d3 = v[3].x * w2.x + v[3].y * w2.y + v[3].z * w2.z + v[3].w * w2.w; \
        float _a01 = (sub & 1) ? _d1 : _d0;                                  \
        float _s01 = (sub & 1) ? _d0 : _d1;                                  \
        _a01 += __shfl_xor_sync(0xffffffffu, _s01, 1);                       \
        float _a23 = (sub & 1) ? _d3 : _d2;                                  \
        float _s23 = (sub & 1) ? _d2 : _d3;                                  \
        _a23 += __shfl_xor_sync(0xffffffffu, _s23, 1);                       \
        float _keep = (sub & 2) ? _a23 : _a01;                               \
        float _send = (sub & 2) ? _a01 : _a23;                               \
        float _s = _keep + __shfl_xor_sync(0xffffffffu, _send, 2);           \
        _s += __shfl_xor_sync(0xffffffffu, _s, 4);                           \
        _s += __shfl_xor_sync(0xffffffffu, _s, 8);                           \
        if (sub < 4) dbuf[sub * 16 + grp] = _s;                              \
                                                                             \
        /* s1 = item[n].wa1 (independent of dbuf -> overlaps d-transpose) */ \
        float _p = it0 * wa1s[lane] + it1 * wa1s[32 + lane];                 \
        _Pragma("unroll")                                                    \
        for (int _o = 16; _o > 0; _o >>= 1)                                  \
            _p += __shfl_xor_sync(0xffffffffu, _p, _o);                      \
        __syncthreads();                                                     \
                                                                             \
        /* unnormalized weights from dbuf (broadcast LDS), local exp, mask */\
        float _x0 = _p + dbuf[grp];                                          \
        float _x1 = _p + dbuf[16 + grp];                                     \
        float _x2 = _p + dbuf[32 + grp];                                     \
        float _x3 = _p + dbuf[48 + grp];                                     \
        _x0 = _x0 > 0.f ? _x0 : ALPHA * _x0;                                 \
        _x1 = _x1 > 0.f ? _x1 : ALPHA * _x1;                                 \
        _x2 = _x2 > 0.f ? _x2 : ALPHA * _x2;                                 \
        _x3 = _x3 > 0.f ? _x3 : ALPHA * _x3;                                 \
        _x0 = (mk & 1) ? __expf(_x0) : 0.f;                                  \
        _x1 = (mk & 2) ? __expf(_x1) : 0.f;                                  \
        _x2 = (mk & 4) ? __expf(_x2) : 0.f;                                  \
        _x3 = (mk & 8) ? __expf(_x3) : 0.f;                                  \
                                                                             \
        /* unnormalized weighted sum from registers */                       \
        float4 _acc;                                                         \
        _acc.x = _x0 * v[0].x; _acc.y = _x0 * v[0].y;                        \
        _acc.z = _x0 * v[0].z; _acc.w = _x0 * v[0].w;                        \
        _acc.x = fmaf(_x1, v[1].x, _acc.x); _acc.y = fmaf(_x1, v[1].y, _acc.y); \
        _acc.z = fmaf(_x1, v[1].z, _acc.z); _acc.w = fmaf(_x1, v[1].w, _acc.w); \
        _acc.x = fmaf(_x2, v[2].x, _acc.x); _acc.y = fmaf(_x2, v[2].y, _acc.y); \
        _acc.z = fmaf(_x2, v[2].z, _acc.z); _acc.w = fmaf(_x2, v[2].w, _acc.w); \
        _acc.x = fmaf(_x3, v[3].x, _acc.x); _acc.y = fmaf(_x3, v[3].y, _acc.y); \
        _acc.z = fmaf(_x3, v[3].z, _acc.z); _acc.w = fmaf(_x3, v[3].w, _acc.w); \
        float _smp = (_x0 + _x1) + (_x2 + _x3);                              \
        _acc.x += __shfl_xor_sync(0xffffffffu, _acc.x, 16);                  \
        _acc.y += __shfl_xor_sync(0xffffffffu, _acc.y, 16);                  \
        _acc.z += __shfl_xor_sync(0xffffffffu, _acc.z, 16);                  \
        _acc.w += __shfl_xor_sync(0xffffffffu, _acc.w, 16);                  \
        _smp   += __shfl_xor_sync(0xffffffffu, _smp, 16);                    \
        if (lane < 16)                                                       \
            *reinterpret_cast<float4*>(&part[w * 64 + sub * 4]) = _acc;      \
        if (lane == 0) smsum[w] = _smp;                                      \
        __syncthreads();                                                     \
                                                                             \
        /* epilogue: reduce 8 warp partials, divide once, add residual */    \
        if (t < 64) {                                                        \
            float _r = (part[t]       + part[64 + t])  + (part[128 + t]      \
                     + part[192 + t]) + (part[256 + t] + part[320 + t])      \
                     + (part[384 + t] + part[448 + t]);                      \
            float _st = (smsum[0] + smsum[1]) + (smsum[2] + smsum[3])        \
                      + (smsum[4] + smsum[5]) + (smsum[6] + smsum[7]);       \
            out[_b + t] = _r * (1.0f / _st) + ((w == 0) ? it0 : it1);        \
        }                                                                    \
    }

__global__ __launch_bounds__(256, 4) void gat_kernel(
    const float* __restrict__ item,
    const float* __restrict__ ent,
    const int*   __restrict__ adj,
    const float* __restrict__ W,
    const float* __restrict__ a,
    float*       __restrict__ out)
{
    __shared__ float wa1s[64];
    __shared__ float wa2s[64];
    __shared__ float dbuf[64];
    __shared__ float part[8 * 64];
    __shared__ float smsum[8];

    const int t    = threadIdx.x;
    const int lane = t & 31;
    const int sub  = t & 15;
    const int grp  = t >> 4;
    const int w    = t >> 5;
    const int S    = gridDim.x;

    // --- Prologue: wa1 = W@a1, wa2 = W@a2 (once per CTA) ---
    {
        const int f = t >> 2, q = t & 3;
        const float* wr = W + f * 64 + q * 16;
        float p1 = 0.f, p2 = 0.f;
#pragma unroll
        for (int i = 0; i < 4; ++i) {
            float4 wv = *reinterpret_cast<const float4*>(wr + i * 4);
            float4 y1 = *reinterpret_cast<const float4*>(a + q * 16 + i * 4);
            float4 y2 = *reinterpret_cast<const float4*>(a + 64 + q * 16 + i * 4);
            p1 += wv.x * y1.x + wv.y * y1.y + wv.z * y1.z + wv.w * y1.w;
            p2 += wv.x * y2.x + wv.y * y2.y + wv.z * y2.z + wv.w * y2.w;
        }
        p1 += __shfl_xor_sync(0xffffffffu, p1, 1);
        p1 += __shfl_xor_sync(0xffffffffu, p1, 2);
        p2 += __shfl_xor_sync(0xffffffffu, p2, 1);
        p2 += __shfl_xor_sync(0xffffffffu, p2, 2);
        if (q == 0) { wa1s[f] = p1; wa2s[f] = p2; }
    }
    __syncthreads();
    const float4 w2 = *reinterpret_cast<const float4*>(&wa2s[sub * 4]);

    // --- 3-stage pipeline: adj+item 2 ahead, predicated tile 1 ahead ---
    float4 vA[4], vB[4];
    int   j0A, j1A, j0B, j1B, j0C, j1C;
    float i0A, i1A, i0B, i1B, i0C, i1C;
    int   mkA, mkB;

    int n = blockIdx.x;
    LOADJI(n, j0A, j1A, i0A, i1A);
    if (n + S < N_ITEMS) LOADJI(n + S, j0B, j1B, i0B, i1B);
    MASKOF(j0A, j1A, mkA);
    LOADT_P(n, vA, mkA);

    while (true) {
        const int nB = n + S;
        const int nC = n + 2 * S;
        if (nB < N_ITEMS) {
            MASKOF(j0B, j1B, mkB);
            LOADT_P(nB, vB, mkB);
            if (nC < N_ITEMS) LOADJI(nC, j0C, j1C, i0C, i1C);
        }
        BODY(n, vA, mkA, i0A, i1A);
        if (nB >= N_ITEMS) break;

        const int nD = n + 3 * S;
        if (nC < N_ITEMS) {
            MASKOF(j0C, j1C, mkA);
            LOADT_P(nC, vA, mkA);
            if (nD < N_ITEMS) LOADJI(nD, j0A, j1A, i0A, i1A);
        }
        BODY(nB, vB, mkB, i0B, i1B);
        if (nC >= N_ITEMS) break;

        // rotate: current <- nC (tile in vA/mkA), flags/items shuffle down
        j0B = j0A; j1B = j1A; i0B = i0A; i1B = i1A;   // nD's -> next slot
        j0A = j0C; j1A = j1C; i0A = i0C; i1A = i1C;   // nC's -> current slot
        n = nC;
    }
}

extern "C" void kernel_launch(void* const* d_in, const int* in_sizes, int n_in,
                              void* d_out, int out_size) {
    const float* item = (const float*)d_in[0];
    const float* ent  = (const float*)d_in[1];
    const int*   adj  = (const int*)d_in[2];
    const float* W    = (const float*)d_in[3];
    const float* a    = (const float*)d_in[4];
    float* out = (float*)d_out;

    gat_kernel<<<GRID, 256>>>(item, ent, adj, W, a, out);
}

// round 9
// speedup vs baseline: 1.4366x; 1.0100x over previous
#include <cuda_runtime.h>

#define N_ITEMS 20000
#define ALPHA 0.2f
#define GRID 608                   // 4 CTAs/SM x 152 SMs (persistent)
#define SI (GRID * 64)             // adj/item/out stride per grid step (elems)
#define SE ((size_t)GRID * 4096)   // entity stride per grid step (floats)

#define BARS(id) asm volatile("bar.sync %0, 256;"   :: "n"(id) : "memory")
#define BARA(id) asm volatile("bar.arrive %0, 256;" :: "n"(id) : "memory")

// Predicated tile load from ballot masks: row m=k*16+grp live iff its mask bit set.
#define LOADT(base, V, M0, M1)                                                          \
    V[0] = ((M0 >> grp) & 1u)        ? *reinterpret_cast<const float4*>((base) + t * 4)        : make_float4(0.f,0.f,0.f,0.f); \
    V[1] = ((M0 >> (16 + grp)) & 1u) ? *reinterpret_cast<const float4*>((base) + 1024 + t * 4) : make_float4(0.f,0.f,0.f,0.f); \
    V[2] = ((M1 >> grp) & 1u)        ? *reinterpret_cast<const float4*>((base) + 2048 + t * 4) : make_float4(0.f,0.f,0.f,0.f); \
    V[3] = ((M1 >> (16 + grp)) & 1u) ? *reinterpret_cast<const float4*>((base) + 3072 + t * 4) : make_float4(0.f,0.f,0.f,0.f);

// Prefetch next row: ballot masks from pre-loaded adj regs, predicated tile LDGs,
// then adj for row n+2 and role-specific item prefetches.
#define PREF(VN, _nn)                                                        \
    if ((_nn) < N_ITEMS) {                                                   \
        bm0 = __ballot_sync(0xffffffffu, jn0 > 0);                           \
        bm1 = __ballot_sync(0xffffffffu, jn1 > 0);                           \
        LOADT(enp + SE, VN, bm0, bm1);                                       \
        if ((_nn) + GRID < N_ITEMS) {                                        \
            jn0 = adp[2 * SI + lane];                                        \
            jn1 = adp[2 * SI + 32 + lane];                                   \
        }                                                                    \
        if (w == 6) { ia = itp[SI + lane]; ib = itp[SI + 32 + lane]; }       \
        if (isE)    { ieN = itp[SI + fepi]; }                                \
    }

// Process current row (tile in VC, masks bm0/bm1); prefetch next into VN.
#define STEP(VC, VN)                                                         \
{                                                                            \
    /* d-phase (all warps): 16 FFMA + 5-shfl transpose reduce */             \
    float _d0 = VC[0].x*w2.x + VC[0].y*w2.y + VC[0].z*w2.z + VC[0].w*w2.w;   \
    float _d1 = VC[1].x*w2.x + VC[1].y*w2.y + VC[1].z*w2.z + VC[1].w*w2.w;   \
    float _d2 = VC[2].x*w2.x + VC[2].y*w2.y + VC[2].z*w2.z + VC[2].w*w2.w;   \
    float _d3 = VC[3].x*w2.x + VC[3].y*w2.y + VC[3].z*w2.z + VC[3].w*w2.w;   \
    float _a01 = (sub & 1) ? _d1 : _d0;                                      \
    float _s01 = (sub & 1) ? _d0 : _d1;                                      \
    _a01 += __shfl_xor_sync(0xffffffffu, _s01, 1);                           \
    float _a23 = (sub & 1) ? _d3 : _d2;                                      \
    float _s23 = (sub & 1) ? _d2 : _d3;                                      \
    _a23 += __shfl_xor_sync(0xffffffffu, _s23, 1);                           \
    float _keep = (sub & 2) ? _a23 : _a01;                                   \
    float _send = (sub & 2) ? _a01 : _a23;                                   \
    float _s = _keep + __shfl_xor_sync(0xffffffffu, _send, 2);               \
    _s += __shfl_xor_sync(0xffffffffu, _s, 4);                               \
    _s += __shfl_xor_sync(0xffffffffu, _s, 8);                               \
    if (sub < 4) dbuf[sub * 16 + grp] = _s;                                  \
    if (w == 6) { /* s1 for THIS row from prefetched ia/ib */                \
        float _p = ia * wa1s[lane] + ib * wa1s[32 + lane];                   \
        _p += __shfl_xor_sync(0xffffffffu, _p, 16);                          \
        _p += __shfl_xor_sync(0xffffffffu, _p, 8);                           \
        _p += __shfl_xor_sync(0xffffffffu, _p, 4);                           \
        _p += __shfl_xor_sync(0xffffffffu, _p, 2);                           \
        _p += __shfl_xor_sync(0xffffffffu, _p, 1);                           \
        if (lane == 0) s1s = _p;                                             \
    }                                                                        \
    const int _nn = n + GRID;                                                \
    if (isX) {                                                               \
        BARS(1);   /* wait: dbuf + s1s ready */                             \
        const unsigned _msk = (w == 2) ? bm0 : bm1;                          \
        float _e = s1s + dbuf[(w - 2) * 32 + lane];                          \
        _e = fmaxf(_e, ALPHA * _e);                                          \
        float _x = ((_msk >> lane) & 1u) ? __expf(_e) : 0.f;                 \
        abuf[(lane & 15) * 4 + (w - 2) * 2 + (lane >> 4)] = _x;              \
        PREF(VN, _nn);                                                       \
        float _sm = _x;                                                      \
        _sm += __shfl_xor_sync(0xffffffffu, _sm, 16);                        \
        _sm += __shfl_xor_sync(0xffffffffu, _sm, 8);                         \
        _sm += __shfl_xor_sync(0xffffffffu, _sm, 4);                         \
        _sm += __shfl_xor_sync(0xffffffffu, _sm, 2);                         \
        _sm += __shfl_xor_sync(0xffffffffu, _sm, 1);                         \
        if (lane == 0) smsum[w - 2] = _sm;                                   \
        BARS(2);                                                             \
    } else {                                                                 \
        BARA(1);   /* producer arrive; overlap next LDGs with x-comp */      \
        PREF(VN, _nn);                                                       \
        BARS(2);   /* wait: abuf + smsum ready */                            \
    }                                                                        \
    /* acc phase (all warps): one LDS.128 of att + 16 FFMA */                \
    const float4 _at = *reinterpret_cast<const float4*>(&abuf[grp * 4]);     \
    float4 _acc;                                                             \
    _acc.x = _at.x * VC[0].x; _acc.y = _at.x * VC[0].y;                      \
    _acc.z = _at.x * VC[0].z; _acc.w = _at.x * VC[0].w;                      \
    _acc.x = fmaf(_at.y, VC[1].x, _acc.x); _acc.y = fmaf(_at.y, VC[1].y, _acc.y); \
    _acc.z = fmaf(_at.y, VC[1].z, _acc.z); _acc.w = fmaf(_at.y, VC[1].w, _acc.w); \
    _acc.x = fmaf(_at.z, VC[2].x, _acc.x); _acc.y = fmaf(_at.z, VC[2].y, _acc.y); \
    _acc.z = fmaf(_at.z, VC[2].z, _acc.z); _acc.w = fmaf(_at.z, VC[2].w, _acc.w); \
    _acc.x = fmaf(_at.w, VC[3].x, _acc.x); _acc.y = fmaf(_at.w, VC[3].y, _acc.y); \
    _acc.z = fmaf(_at.w, VC[3].z, _acc.z); _acc.w = fmaf(_at.w, VC[3].w, _acc.w); \
    _acc.x += __shfl_xor_sync(0xffffffffu, _acc.x, 16);                      \
    _acc.y += __shfl_xor_sync(0xffffffffu, _acc.y, 16);                      \
    _acc.z += __shfl_xor_sync(0xffffffffu, _acc.z, 16);                      \
    _acc.w += __shfl_xor_sync(0xffffffffu, _acc.w, 16);                      \
    if (lane < 16)                                                           \
        *reinterpret_cast<float4*>(&part[w * 64 + sub * 4]) = _acc;          \
    if (isE) {                                                               \
        BARS(3);   /* wait: part ready */                                    \
        float _r = (part[fepi]       + part[64 + fepi])                      \
                 + (part[128 + fepi] + part[192 + fepi])                     \
                 + (part[256 + fepi] + part[320 + fepi])                     \
                 + (part[384 + fepi] + part[448 + fepi]);                    \
        oup[fepi] = _r * (1.0f / (smsum[0] + smsum[1])) + ie;                \
        ie = ieN;                                                            \
    } else {                                                                 \
        BARA(3);                                                             \
    }                                                                        \
    enp += SE; adp += SI; itp += SI; oup += SI;                              \
}

__global__ __launch_bounds__(256, 4) void gat_kernel(
    const float* __restrict__ item,
    const float* __restrict__ ent,
    const int*   __restrict__ adj,
    const float* __restrict__ W,
    const float* __restrict__ a,
    float*       __restrict__ out)
{
    __shared__ float wa1s[64], wa2s[64];
    __shared__ float dbuf[64];
    __shared__ float abuf[64];     // unnormalized att, layout [(m&15)*4 + (m>>4)]
    __shared__ float part[8 * 64];
    __shared__ float smsum[2];
    __shared__ float s1s;

    const int t    = threadIdx.x;
    const int lane = t & 31;
    const int sub  = t & 15;
    const int grp  = t >> 4;
    const int w    = t >> 5;
    const bool isX = (w == 2) || (w == 3);   // x-value producer warps
    const bool isE = (w == 4) || (w == 5);   // epilogue warps
    const int fepi = lane + (w - 4) * 32;    // epilogue f (valid when isE)

    // --- Prologue: wa1 = W@a1, wa2 = W@a2 (once per CTA) ---
    {
        const int f = t >> 2, q = t & 3;
        const float* wr = W + f * 64 + q * 16;
        float p1 = 0.f, p2 = 0.f;
#pragma unroll
        for (int i = 0; i < 4; ++i) {
            float4 wv = *reinterpret_cast<const float4*>(wr + i * 4);
            float4 y1 = *reinterpret_cast<const float4*>(a + q * 16 + i * 4);
            float4 y2 = *reinterpret_cast<const float4*>(a + 64 + q * 16 + i * 4);
            p1 += wv.x * y1.x + wv.y * y1.y + wv.z * y1.z + wv.w * y1.w;
            p2 += wv.x * y2.x + wv.y * y2.y + wv.z * y2.z + wv.w * y2.w;
        }
        p1 += __shfl_xor_sync(0xffffffffu, p1, 1);
        p1 += __shfl_xor_sync(0xffffffffu, p1, 2);
        p2 += __shfl_xor_sync(0xffffffffu, p2, 1);
        p2 += __shfl_xor_sync(0xffffffffu, p2, 2);
        if (q == 0) { wa1s[f] = p1; wa2s[f] = p2; }
    }
    __syncthreads();
    const float4 w2 = *reinterpret_cast<const float4*>(&wa2s[sub * 4]);

    int n = blockIdx.x;
    const float* enp = ent + (size_t)n * 4096;
    const int*   adp = adj + n * 64;
    const float* itp = item + n * 64;
    float*       oup = out + n * 64;

    // --- Prime row n ---
    int jn0 = adp[lane];
    int jn1 = adp[32 + lane];
    unsigned bm0 = __ballot_sync(0xffffffffu, jn0 > 0);
    unsigned bm1 = __ballot_sync(0xffffffffu, jn1 > 0);
    float4 vA[4], vB[4];
    LOADT(enp, vA, bm0, bm1);
    float ia = 0.f, ib = 0.f, ie = 0.f, ieN = 0.f;
    if (w == 6) { ia = itp[lane]; ib = itp[32 + lane]; }
    if (isE)    { ie = itp[fepi]; }
    if (n + GRID < N_ITEMS) {              // adj for row n+1
        jn0 = adp[SI + lane];
        jn1 = adp[SI + 32 + lane];
    }

    while (true) {
        STEP(vA, vB);
        n += GRID; if (n >= N_ITEMS) break;
        STEP(vB, vA);
        n += GRID; if (n >= N_ITEMS) break;
    }
}

extern "C" void kernel_launch(void* const* d_in, const int* in_sizes, int n_in,
                              void* d_out, int out_size) {
    const float* item = (const float*)d_in[0];
    const float* ent  = (const float*)d_in[1];
    const int*   adj  = (const int*)d_in[2];
    const float* W    = (const float*)d_in[3];
    const float* a    = (const float*)d_in[4];
    float* out = (float*)d_out;

    gat_kernel<<<GRID, 256>>>(item, ent, adj, W, a, out);
}

// round 10
// speedup vs baseline: 1.8050x; 1.2565x over previous
#include <cuda_runtime.h>

#define N_ITEMS 20000
#define ALPHA 0.2f
#define GRID 608
#define NGROUP (GRID * 2)      // 1216 independent row pipelines
#define S64 (NGROUP * 64)      // element stride per step for 64-wide arrays

#define BARG() asm volatile("bar.sync %0, 128;" :: "r"(barid) : "memory")

__global__ __launch_bounds__(256, 4) void gat_kernel(
    const float* __restrict__ item,
    const float* __restrict__ ent,
    const int*   __restrict__ adj,
    const float* __restrict__ W,
    const float* __restrict__ a,
    float*       __restrict__ out)
{
    __shared__ float wa1s[64], wa2s[64];
    __shared__ float dbuf[2][64];      // per group
    __shared__ float xbuf[2][64];
    __shared__ float part[2][256];
    __shared__ float smsum[2][2][2];   // [group][row parity][warp 0/1]
    __shared__ float s1buf[2];

    const int t    = threadIdx.x;
    const int gi   = t >> 7;        // group in CTA (0/1)
    const int gt   = t & 127;       // thread in group
    const int lane = t & 31;
    const int wg   = gt >> 5;       // warp in group 0..3
    const int mB   = gt >> 4;       // m base 0..7
    const int fs   = gt & 15;       // f-slot (float4 index within row)
    const int fe   = gt - 64;       // epilogue f (valid for wg>=2)
    const int barid = 1 + gi;

    // --- wa1 = W@a1, wa2 = W@a2 (once per CTA, 256 threads) ---
    {
        const int f = t >> 2, q = t & 3;
        const float* wr = W + f * 64 + q * 16;
        float p1 = 0.f, p2 = 0.f;
#pragma unroll
        for (int i = 0; i < 4; ++i) {
            float4 wv = *(const float4*)(wr + i * 4);
            float4 y1 = *(const float4*)(a + q * 16 + i * 4);
            float4 y2 = *(const float4*)(a + 64 + q * 16 + i * 4);
            p1 += wv.x*y1.x + wv.y*y1.y + wv.z*y1.z + wv.w*y1.w;
            p2 += wv.x*y2.x + wv.y*y2.y + wv.z*y2.z + wv.w*y2.w;
        }
        p1 += __shfl_xor_sync(~0u, p1, 1); p1 += __shfl_xor_sync(~0u, p1, 2);
        p2 += __shfl_xor_sync(~0u, p2, 1); p2 += __shfl_xor_sync(~0u, p2, 2);
        if (q == 0) { wa1s[f] = p1; wa2s[f] = p2; }
    }
    __syncthreads();
    const float4 w2 = *(const float4*)&wa2s[fs * 4];

    int n   = blockIdx.x * 2 + gi;   // this group's first row
    int off = n * 64;

    // --- Prime row n ---
    int j0 = adj[off + lane], j1 = adj[off + 32 + lane];
    unsigned bm0 = __ballot_sync(~0u, j0 > 0);
    unsigned bm1 = __ballot_sync(~0u, j1 > 0);
    float4 v[8];
    {
        const float* eb = ent + (size_t)off * 64;
#pragma unroll
        for (int c = 0; c < 8; ++c) {
            const int m = mB + 8 * c;
            const bool lv = (m < 32) ? ((bm0 >> m) & 1u) : ((bm1 >> (m - 32)) & 1u);
            v[c] = lv ? *(const float4*)(eb + (size_t)(gt + 128 * c) * 4)
                      : make_float4(0.f, 0.f, 0.f, 0.f);
        }
    }
    float ia = 0.f, ib = 0.f, iePrev = 0.f, ieCur = 0.f;
    if (wg == 2) { ia = item[off + lane]; ib = item[off + 32 + lane]; }
    if (wg >= 2) { ieCur = item[off + fe]; }
    bool hasN = (n + NGROUP) < N_ITEMS;
    int jn0 = 0, jn1 = 0;
    if (hasN) { jn0 = adj[off + S64 + lane]; jn1 = adj[off + S64 + 32 + lane]; }

    int par = 0, offPrev = -1;

    while (true) {
        // ---- window A: d-phase (all warps) + s1 (warp 2) ----
        float dd[8];
#pragma unroll
        for (int c = 0; c < 8; ++c)
            dd[c] = v[c].x*w2.x + v[c].y*w2.y + v[c].z*w2.z + v[c].w*w2.w;
        // folded butterfly: 8 values over 16 lanes in 8 shfls; lane j ends with d_{j&7}
        float e0 = ((lane&1)? dd[1]:dd[0]) + __shfl_xor_sync(~0u, (lane&1)? dd[0]:dd[1], 1);
        float e1 = ((lane&1)? dd[3]:dd[2]) + __shfl_xor_sync(~0u, (lane&1)? dd[2]:dd[3], 1);
        float e2 = ((lane&1)? dd[5]:dd[4]) + __shfl_xor_sync(~0u, (lane&1)? dd[4]:dd[5], 1);
        float e3 = ((lane&1)? dd[7]:dd[6]) + __shfl_xor_sync(~0u, (lane&1)? dd[6]:dd[7], 1);
        float f0 = ((lane&2)? e1:e0) + __shfl_xor_sync(~0u, (lane&2)? e0:e1, 2);
        float f1 = ((lane&2)? e3:e2) + __shfl_xor_sync(~0u, (lane&2)? e2:e3, 2);
        float g0 = ((lane&4)? f1:f0) + __shfl_xor_sync(~0u, (lane&4)? f0:f1, 4);
        g0 += __shfl_xor_sync(~0u, g0, 8);
        if (!(lane & 8)) dbuf[gi][mB + 8 * (lane & 7)] = g0;
        if (wg == 2) {
            float p = ia * wa1s[lane] + ib * wa1s[32 + lane];
            p += __shfl_xor_sync(~0u, p, 16);
            p += __shfl_xor_sync(~0u, p, 8);
            p += __shfl_xor_sync(~0u, p, 4);
            p += __shfl_xor_sync(~0u, p, 2);
            p += __shfl_xor_sync(~0u, p, 1);
            if (lane == 0) s1buf[gi] = p;
        }
        BARG();

        // ---- window B: warps 0-1: x + sum; warps 2-3: prev-row epilogue + prefetch ----
        if (wg < 2) {
            float e = s1buf[gi] + dbuf[gi][gt];
            e = fmaxf(e, ALPHA * e);
            const unsigned mk = wg ? bm1 : bm0;
            const float x = ((mk >> lane) & 1u) ? __expf(e) : 0.f;
            xbuf[gi][gt] = x;
            float sm = x;
            sm += __shfl_xor_sync(~0u, sm, 16);
            sm += __shfl_xor_sync(~0u, sm, 8);
            sm += __shfl_xor_sync(~0u, sm, 4);
            sm += __shfl_xor_sync(~0u, sm, 2);
            sm += __shfl_xor_sync(~0u, sm, 1);
            if (lane == 0) smsum[gi][par][wg] = sm;
        } else {
            if (offPrev >= 0) {
                const float r = (part[gi][fe] + part[gi][64 + fe])
                              + (part[gi][128 + fe] + part[gi][192 + fe]);
                const float inv = 1.0f / (smsum[gi][par ^ 1][0] + smsum[gi][par ^ 1][1]);
                out[offPrev + fe] = r * inv + iePrev;
            }
            iePrev = ieCur;
            if (hasN) {
                ieCur = item[off + S64 + fe];
                if (wg == 2) { ia = item[off + S64 + lane]; ib = item[off + S64 + 32 + lane]; }
            }
        }
        BARG();

        // ---- window C: acc(current) interleaved with next-row tile loads ----
        bm0 = __ballot_sync(~0u, hasN && jn0 > 0);
        bm1 = __ballot_sync(~0u, hasN && jn1 > 0);
        const bool hasNN = (n + 2 * NGROUP) < N_ITEMS;
        if (hasNN) { jn0 = adj[off + 2*S64 + lane]; jn1 = adj[off + 2*S64 + 32 + lane]; }
        {
            const float* ebN = ent + (size_t)(off + S64) * 64;
            float4 acc = make_float4(0.f, 0.f, 0.f, 0.f);
#pragma unroll
            for (int c = 0; c < 8; ++c) {
                const float xv = xbuf[gi][mB + 8 * c];
                acc.x = fmaf(xv, v[c].x, acc.x);
                acc.y = fmaf(xv, v[c].y, acc.y);
                acc.z = fmaf(xv, v[c].z, acc.z);
                acc.w = fmaf(xv, v[c].w, acc.w);
                const int m = mB + 8 * c;   // next row, same m layout
                const bool lv = (m < 32) ? ((bm0 >> m) & 1u) : ((bm1 >> (m - 32)) & 1u);
                v[c] = lv ? *(const float4*)(ebN + (size_t)(gt + 128 * c) * 4)
                          : make_float4(0.f, 0.f, 0.f, 0.f);
            }
            acc.x += __shfl_xor_sync(~0u, acc.x, 16);
            acc.y += __shfl_xor_sync(~0u, acc.y, 16);
            acc.z += __shfl_xor_sync(~0u, acc.z, 16);
            acc.w += __shfl_xor_sync(~0u, acc.w, 16);
            if (lane < 16) *(float4*)&part[gi][wg * 64 + lane * 4] = acc;
        }
        offPrev = off; off += S64; n += NGROUP; par ^= 1; hasN = hasNN;
        if (n >= N_ITEMS) break;
    }

    // ---- drain: epilogue for the final row ----
    BARG();
    if (wg >= 2) {
        const float r = (part[gi][fe] + part[gi][64 + fe])
                      + (part[gi][128 + fe] + part[gi][192 + fe]);
        const float inv = 1.0f / (smsum[gi][par ^ 1][0] + smsum[gi][par ^ 1][1]);
        out[offPrev + fe] = r * inv + iePrev;
    }
}

extern "C" void kernel_launch(void* const* d_in, const int* in_sizes, int n_in,
                              void* d_out, int out_size) {
    const float* item = (const float*)d_in[0];
    const float* ent  = (const float*)d_in[1];
    const int*   adj  = (const int*)d_in[2];
    const float* W    = (const float*)d_in[3];
    const float* a    = (const float*)d_in[4];
    float* out = (float*)d_out;

    gat_kernel<<<GRID, 256>>>(item, ent, adj, W, a, out);
}